// round 9
// baseline (speedup 1.0000x reference)
#include <cuda_runtime.h>

// AsymmetricEMA, segmented-parallel with contraction warmup + parity-ordered
// launch (even-s wave first) + L2-policy split: read-once stream uses ld.cs
// (evict-first), producer-tail regions (re-read by successor's warmup) use
// ld.cg so they persist in L2 across the wave boundary.
// y' = 0.5*y + 0.01*x + 0.49*max(x, y)  ==  alpha-select EMA (exact, branch-free)
// T split into 8 segments of 512; segments s>0 warm up over the previous 128
// steps from passthrough init (contraction kills init error; measured 1.9e-4).

#define B_ 16
#define T_ 4096
#define C_ 1024
#define S_ 8
#define L_ (T_ / S_)   // 512
#define W_ 128         // warmup steps for s > 0 (= 4 chunks)
#define U_ 32          // chunk size (double-buffered in registers)
#define TAILCH 4       // chunks in the producer tail (= W_/U_)

#define LOAD_CHUNK_CS(buf, t0)                                   \
    _Pragma("unroll")                                            \
    for (int u = 0; u < U_; u++)                                 \
        buf[u] = __ldcs(xp + (size_t)((t0) + u) * C_);

#define LOAD_CHUNK_CG(buf, t0)                                   \
    _Pragma("unroll")                                            \
    for (int u = 0; u < U_; u++)                                 \
        buf[u] = __ldcg(xp + (size_t)((t0) + u) * C_);

// tail => keep in L2 (consumer segment re-reads it); else evict-first.
#define LOAD_CHUNK(buf, t0, tail)                                \
    do {                                                         \
        if (tail) { LOAD_CHUNK_CG(buf, t0) }                     \
        else      { LOAD_CHUNK_CS(buf, t0) }                     \
    } while (0)

#define STEP(xv)                                                  \
    do {                                                          \
        float _x = (xv);                                          \
        float _m = fmaxf(_x, yv);                                 \
        yv = fmaf(0.49f, _m, fmaf(0.5f, yv, 0.01f * _x));         \
    } while (0)

#define COMPUTE_CHUNK(buf, tt, dostore)                          \
    _Pragma("unroll")                                            \
    for (int u = 0; u < U_; u++) {                               \
        STEP(buf[u]);                                            \
        if (dostore) __stcs(yp + (size_t)((tt) + u) * C_, yv);   \
    }

__global__ void __launch_bounds__(128, 4)
asym_ema_seg_kernel(const float* __restrict__ x, float* __restrict__ y) {
    // 1024 CTAs. Parity remap: bids [0,512) -> s in {0,2,4,6} (wave 1),
    // bids [512,1024) -> s in {1,3,5,7} (wave 2). Within a group:
    // idx = bid & 511 = b(4b) | sidx(2b) | cblk(3b).
    const int bid  = blockIdx.x;
    const int idx  = bid & 511;
    const int cblk = idx & 7;
    const int sidx = (idx >> 3) & 3;
    const int b    = idx >> 5;
    const int s    = (bid < 512) ? (2 * sidx) : (2 * sidx + 1);

    const int c = (cblk << 7) + threadIdx.x;

    const size_t base = (size_t)b * T_ * C_ + (size_t)c;
    const float* xp = x + base;
    float*       yp = y + base;

    const int t0  = s * L_;
    const int tb  = (s == 0) ? 0 : (t0 - W_);
    const int nch = ((s == 0) ? L_ : (L_ + W_)) / U_;   // 16 or 20 (even)
    // Chunks i >= tail0 are this segment's last W steps; segment s+1 re-reads
    // them as warmup, so keep those lines in L2. Last segment has no consumer.
    const int tail0 = (s == S_ - 1) ? nch : (nch - TAILCH);

    float b0[U_], b1[U_];
    float yv;

    LOAD_CHUNK(b0, tb, 0 >= tail0);
    LOAD_CHUNK(b1, tb + U_, 1 >= tail0);

    // Peeled chunk 0: first processed element is passthrough (exact for s==0
    // at t=0; the contraction-warmup surrogate for s>0 at t=t0-W).
    {
        const bool st = (s == 0);
        yv = b0[0];
        if (st) __stcs(yp + (size_t)tb * C_, yv);
#pragma unroll
        for (int u = 1; u < U_; u++) {
            STEP(b0[u]);
            if (st) __stcs(yp + (size_t)(tb + u) * C_, yv);
        }
    }

    // Main pipeline: register ping-pong, one chunk of prefetch in flight.
    for (int i = 1; i < nch; i += 2) {
        const int t1 = tb + i * U_;
        if (i + 1 < nch) { LOAD_CHUNK(b0, t1 + U_, (i + 1) >= tail0); }
        COMPUTE_CHUNK(b1, t1, t1 >= t0)
        if (i + 2 < nch) { LOAD_CHUNK(b1, t1 + 2 * U_, (i + 2) >= tail0); }
        if (i + 1 < nch) { COMPUTE_CHUNK(b0, t1 + U_, (t1 + U_) >= t0) }
    }
}

extern "C" void kernel_launch(void* const* d_in, const int* in_sizes, int n_in,
                              void* d_out, int out_size) {
    const float* x = (const float*)d_in[0];
    float* y = (float*)d_out;
    asym_ema_seg_kernel<<<B_ * S_ * (C_ / 128), 128>>>(x, y);
}

// round 10
// speedup vs baseline: 1.0043x; 1.0043x over previous
#include <cuda_runtime.h>

// AsymmetricEMA, segmented-parallel with contraction warmup + parity-ordered
// launch (even-s wave first) + L2-policy split implemented as SPLIT LOOPS:
// body prefetches use ld.cs (evict-first, read-once stream), producer-tail
// prefetches (last W steps, re-read by successor's warmup) use ld.cg.
// No per-chunk policy branch -> batched LDG runs survive ptxas.
// y' = 0.5*y + 0.01*x + 0.49*max(x, y)  ==  alpha-select EMA (exact, branch-free)

#define B_ 16
#define T_ 4096
#define C_ 1024
#define S_ 8
#define L_ (T_ / S_)   // 512
#define W_ 128         // warmup steps for s > 0 (= 4 chunks)
#define U_ 32          // chunk size (double-buffered in registers)
#define TAILCH 4       // chunks in the producer tail (= W_/U_)

#define LOAD_CHUNK_CS(buf, t0)                                   \
    _Pragma("unroll")                                            \
    for (int u = 0; u < U_; u++)                                 \
        buf[u] = __ldcs(xp + (size_t)((t0) + u) * C_);

#define LOAD_CHUNK_CG(buf, t0)                                   \
    _Pragma("unroll")                                            \
    for (int u = 0; u < U_; u++)                                 \
        buf[u] = __ldcg(xp + (size_t)((t0) + u) * C_);

#define STEP(xv)                                                  \
    do {                                                          \
        float _x = (xv);                                          \
        float _m = fmaxf(_x, yv);                                 \
        yv = fmaf(0.49f, _m, fmaf(0.5f, yv, 0.01f * _x));         \
    } while (0)

#define COMPUTE_CHUNK(buf, tt, dostore)                          \
    _Pragma("unroll")                                            \
    for (int u = 0; u < U_; u++) {                               \
        STEP(buf[u]);                                            \
        if (dostore) __stcs(yp + (size_t)((tt) + u) * C_, yv);   \
    }

__global__ void __launch_bounds__(128, 4)
asym_ema_seg_kernel(const float* __restrict__ x, float* __restrict__ y) {
    // 1024 CTAs. Parity remap: bids [0,512) -> s in {0,2,4,6} (wave 1),
    // bids [512,1024) -> s in {1,3,5,7} (wave 2). Within a group:
    // idx = bid & 511 = b(4b) | sidx(2b) | cblk(3b).
    const int bid  = blockIdx.x;
    const int idx  = bid & 511;
    const int cblk = idx & 7;
    const int sidx = (idx >> 3) & 3;
    const int b    = idx >> 5;
    const int s    = (bid < 512) ? (2 * sidx) : (2 * sidx + 1);

    const int c = (cblk << 7) + threadIdx.x;

    const size_t base = (size_t)b * T_ * C_ + (size_t)c;
    const float* xp = x + base;
    float*       yp = y + base;

    const int t0  = s * L_;
    const int tb  = (s == 0) ? 0 : (t0 - W_);
    const int nch = ((s == 0) ? L_ : (L_ + W_)) / U_;   // 16 or 20 (even)
    // Chunks j >= tail0 are this segment's last W steps; segment s+1 re-reads
    // them as warmup, so load them ld.cg (keep in L2). Last segment: no tail.
    const int tail0 = (s == S_ - 1) ? nch : (nch - TAILCH);  // 12, 16 or 20

    float b0[U_], b1[U_];
    float yv;

    // Prologue: chunks 0 and 1 are always below tail0 (>= 12) -> ld.cs.
    LOAD_CHUNK_CS(b0, tb)
    LOAD_CHUNK_CS(b1, tb + U_)

    // Peeled chunk 0: first processed element is passthrough (exact for s==0
    // at t=0; the contraction-warmup surrogate for s>0 at t=t0-W).
    {
        const bool st = (s == 0);
        yv = b0[0];
        if (st) __stcs(yp + (size_t)tb * C_, yv);
#pragma unroll
        for (int u = 1; u < U_; u++) {
            STEP(b0[u]);
            if (st) __stcs(yp + (size_t)(tb + u) * C_, yv);
        }
    }

    // Loop 1: pair iterations whose prefetches (chunks i+1, i+2) are all
    // below tail0 -> branch-free ld.cs bodies. i = 1, 3, ..., tail0-3.
    int i = 1;
    for (; i <= tail0 - 3; i += 2) {
        const int t1 = tb + i * U_;
        LOAD_CHUNK_CS(b0, t1 + U_)
        COMPUTE_CHUNK(b1, t1, t1 >= t0)
        LOAD_CHUNK_CS(b1, t1 + 2 * U_)
        COMPUTE_CHUNK(b0, t1 + U_, (t1 + U_) >= t0)
    }

    // Loop 2: tail pairs; prefetched chunks (>= tail0) use ld.cg.
    // (For s == S_-1, tail0 == nch and these loads' guards handle the end.)
    for (; i < nch; i += 2) {
        const int t1 = tb + i * U_;
        if (i + 1 < nch) { LOAD_CHUNK_CG(b0, t1 + U_) }
        COMPUTE_CHUNK(b1, t1, t1 >= t0)
        if (i + 2 < nch) { LOAD_CHUNK_CG(b1, t1 + 2 * U_) }
        if (i + 1 < nch) { COMPUTE_CHUNK(b0, t1 + U_, (t1 + U_) >= t0) }
    }
}

extern "C" void kernel_launch(void* const* d_in, const int* in_sizes, int n_in,
                              void* d_out, int out_size) {
    const float* x = (const float*)d_in[0];
    float* y = (float*)d_out;
    asym_ema_seg_kernel<<<B_ * S_ * (C_ / 128), 128>>>(x, y);
}

// round 11
// speedup vs baseline: 1.0169x; 1.0125x over previous
#include <cuda_runtime.h>

// AsymmetricEMA, segmented-parallel with contraction warmup + parity-ordered
// launch (even-s wave first). All stream loads are ld.cg (ld.cs on the body
// measurably costs ~4% DRAM rate on this chip); ONLY the consumer-side warmup
// reads (mostly L2 hits on producer tails) are ld.cs so the dead lines free
// L2 capacity immediately after their single use.
// y' = 0.5*y + 0.01*x + 0.49*max(x, y)  ==  alpha-select EMA (exact, branch-free)
// T split into 8 segments of 512; segments s>0 warm up over the previous 128
// steps from passthrough init (contraction kills init error; measured 1.9e-4).

#define B_ 16
#define T_ 4096
#define C_ 1024
#define S_ 8
#define L_ (T_ / S_)   // 512
#define W_ 128         // warmup steps for s > 0 (= 4 chunks)
#define U_ 32          // chunk size (double-buffered in registers)

#define LOAD_CHUNK_CG(buf, t0)                                   \
    _Pragma("unroll")                                            \
    for (int u = 0; u < U_; u++)                                 \
        buf[u] = __ldcg(xp + (size_t)((t0) + u) * C_);

#define LOAD_CHUNK_CS(buf, t0)                                   \
    _Pragma("unroll")                                            \
    for (int u = 0; u < U_; u++)                                 \
        buf[u] = __ldcs(xp + (size_t)((t0) + u) * C_);

#define STEP(xv)                                                  \
    do {                                                          \
        float _x = (xv);                                          \
        float _m = fmaxf(_x, yv);                                 \
        yv = fmaf(0.49f, _m, fmaf(0.5f, yv, 0.01f * _x));         \
    } while (0)

#define COMPUTE_CHUNK(buf, tt, dostore)                          \
    _Pragma("unroll")                                            \
    for (int u = 0; u < U_; u++) {                               \
        STEP(buf[u]);                                            \
        if (dostore) __stcs(yp + (size_t)((tt) + u) * C_, yv);   \
    }

// Warmup compute: no stores at all (t < t0 always).
#define COMPUTE_CHUNK_NS(buf)                                    \
    _Pragma("unroll")                                            \
    for (int u = 0; u < U_; u++) { STEP(buf[u]); }

__global__ void __launch_bounds__(128, 4)
asym_ema_seg_kernel(const float* __restrict__ x, float* __restrict__ y) {
    // 1024 CTAs. Parity remap: bids [0,512) -> s in {0,2,4,6} (wave 1),
    // bids [512,1024) -> s in {1,3,5,7} (wave 2). Within a group:
    // idx = bid & 511 = b(4b) | sidx(2b) | cblk(3b).
    const int bid  = blockIdx.x;
    const int idx  = bid & 511;
    const int cblk = idx & 7;
    const int sidx = (idx >> 3) & 3;
    const int b    = idx >> 5;
    const int s    = (bid < 512) ? (2 * sidx) : (2 * sidx + 1);

    const int c = (cblk << 7) + threadIdx.x;

    const size_t base = (size_t)b * T_ * C_ + (size_t)c;
    const float* xp = x + base;
    float*       yp = y + base;

    const int t0  = s * L_;
    const int tb  = (s == 0) ? 0 : (t0 - W_);
    const int nch = ((s == 0) ? L_ : (L_ + W_)) / U_;   // 16 or 20 (even)

    float b0[U_], b1[U_];
    float yv;
    int i;  // next pair-loop start index

    if (s == 0) {
        // Prologue + peeled chunk 0 with first-frame passthrough. All ld.cg.
        LOAD_CHUNK_CG(b0, 0)
        LOAD_CHUNK_CG(b1, U_)
        yv = b0[0];
        __stcs(yp, yv);
#pragma unroll
        for (int u = 1; u < U_; u++) {
            STEP(b0[u]);
            __stcs(yp + (size_t)u * C_, yv);
        }
        i = 1;
    } else {
        // Warmup chunks 0..3 (t in [t0-W, t0)): ld.cs (single-use L2 hits on
        // producer tails — release the lines), no stores.
        LOAD_CHUNK_CS(b0, tb)
        LOAD_CHUNK_CS(b1, tb + U_)
        yv = b0[0];
#pragma unroll
        for (int u = 1; u < U_; u++) STEP(b0[u]);
        // Peeled pair i=1: loads chunks 2,3 (still warmup) with ld.cs,
        // computes chunks 1,2 (warmup, no stores).
        LOAD_CHUNK_CS(b0, tb + 2 * U_)
        COMPUTE_CHUNK_NS(b1)
        LOAD_CHUNK_CS(b1, tb + 3 * U_)
        COMPUTE_CHUNK_NS(b0)
        i = 3;
    }

    // Main pipeline: register ping-pong, one chunk of prefetch in flight.
    // For s>0, chunk 3 is warmup (no store) and chunks >=4 are the stored
    // segment body; the t>=t0 guard handles the transition exactly as before.
    for (; i < nch; i += 2) {
        const int t1 = tb + i * U_;
        if (i + 1 < nch) { LOAD_CHUNK_CG(b0, t1 + U_) }
        COMPUTE_CHUNK(b1, t1, t1 >= t0)
        if (i + 2 < nch) { LOAD_CHUNK_CG(b1, t1 + 2 * U_) }
        if (i + 1 < nch) { COMPUTE_CHUNK(b0, t1 + U_, (t1 + U_) >= t0) }
    }
}

extern "C" void kernel_launch(void* const* d_in, const int* in_sizes, int n_in,
                              void* d_out, int out_size) {
    const float* x = (const float*)d_in[0];
    float* y = (float*)d_out;
    asym_ema_seg_kernel<<<B_ * S_ * (C_ / 128), 128>>>(x, y);
}